// round 15
// baseline (speedup 1.0000x reference)
#include <cuda_runtime.h>
#include <cuda_fp16.h>
#include <cstdint>

// ============================================================================
// Constants
// ============================================================================
#define NCH     32          // 32 chunks of K=64
#define TM      128
#define TN      128
#define STAGES  4           // A-only stages now (16KB each)
#define A_STAGE_BYTES (TM * 128)                      // 16384
#define SMEM_TOTAL    67584  // max(4 A-stages = 65536, layer-2 epilogue 128*528)
                             // 2 CTAs/SM: 135168 <= 227KB

// ============================================================================
// Device-global scratch
// X / H: [32768, 2048] fp16 row-major (A operand, cp.async+ldsm path)
// W frag: pre-shuffled mma B fragments:
//   byte = ((((nt*32+cc)*4+ks)*2+wn)*4+j)*512 + lane*16
//   each 16B = the exact 4-reg (b0..b3) fragment lane needs (n16 x k16 block)
// ============================================================================
__device__ __align__(256)  __half g_X[32768ull * 2048];
__device__ __align__(256)  __half g_H[32768ull * 2048];
__device__ __align__(1024) unsigned char g_W1f[8388608];
__device__ __align__(1024) unsigned char g_W2f[8388608];
__device__ float g_b1[2048];
__device__ float g_b2[2048];

// ============================================================================
// Helpers
// ============================================================================
__device__ __forceinline__ uint32_t smem_to_u32(const void* p) {
    uint32_t a;
    asm("{ .reg .u64 t; cvta.to.shared.u64 t, %1; cvt.u32.u64 %0, t; }" : "=r"(a) : "l"(p));
    return a;
}

__device__ __forceinline__ unsigned swz(unsigned off) { return off ^ ((off >> 3) & 0x70); }

__device__ __forceinline__ void cp_async16(uint32_t dst, const void* src) {
    asm volatile("cp.async.cg.shared.global [%0], [%1], 16;" :: "r"(dst), "l"(src));
}

__device__ __forceinline__ void ldsm_x4(uint32_t r[4], uint32_t addr) {
    asm volatile("ldmatrix.sync.aligned.m8n8.x4.shared.b16 {%0,%1,%2,%3}, [%4];"
                 : "=r"(r[0]), "=r"(r[1]), "=r"(r[2]), "=r"(r[3]) : "r"(addr));
}

__device__ __forceinline__ void mma16816(float d[4], const uint32_t a[4], uint32_t b0, uint32_t b1) {
    asm volatile("mma.sync.aligned.m16n8k16.row.col.f32.f16.f16.f32 "
                 "{%0,%1,%2,%3}, {%4,%5,%6,%7}, {%8,%9}, {%0,%1,%2,%3};"
                 : "+f"(d[0]), "+f"(d[1]), "+f"(d[2]), "+f"(d[3])
                 : "r"(a[0]), "r"(a[1]), "r"(a[2]), "r"(a[3]), "r"(b0), "r"(b1));
}

// pack 8 fp32 -> 8 fp16 (uint4)
__device__ __forceinline__ uint4 pack8(const float* v) {
    unsigned h[4];
#pragma unroll
    for (int p = 0; p < 4; p++) {
        __half ha = __float2half_rn(v[2 * p]);
        __half hb = __float2half_rn(v[2 * p + 1]);
        h[p] = (unsigned)__half_as_ushort(ha) | ((unsigned)__half_as_ushort(hb) << 16);
    }
    return make_uint4(h[0], h[1], h[2], h[3]);
}

// ============================================================================
// Fused prep:
//   blocks [0,32768)      : conv_x (q components -> g_X fp16 row-major)
//   blocks [32768,36864)  : W fragment shuffle + biases (2048 blocks per layer)
// ============================================================================
__global__ void prep_all_kernel(const float* __restrict__ qr, const float* __restrict__ qi,
                                const float* __restrict__ qj, const float* __restrict__ qk,
                                const float* __restrict__ w1r, const float* __restrict__ w1i,
                                const float* __restrict__ w1j, const float* __restrict__ w1k,
                                const float* __restrict__ w2r, const float* __restrict__ w2i,
                                const float* __restrict__ w2j, const float* __restrict__ w2k,
                                const float* b1r, const float* b1i, const float* b1j, const float* b1k,
                                const float* b2r, const float* b2i, const float* b2j, const float* b2k) {
    if (blockIdx.x < 32768) {
        unsigned idx = blockIdx.x * blockDim.x + threadIdx.x;
        unsigned n  = idx >> 8;
        unsigned f0 = (idx & 255u) << 3;
        unsigned comp = f0 >> 9, d0 = f0 & 511;
        const float* src = (comp == 0 ? qr : comp == 1 ? qi : comp == 2 ? qj : qk);
        const float4* s4 = (const float4*)(src + (size_t)n * 512 + d0);
        float4 a = s4[0], b = s4[1];
        float v[8] = {a.x, a.y, a.z, a.w, b.x, b.y, b.z, b.w};
        *(uint4*)(g_X + (size_t)n * 2048 + f0) = pack8(v);
    } else {
        unsigned pb = blockIdx.x - 32768;         // 0..4095
        int layer2 = (pb >= 2048);
        unsigned t = (pb & 2047u) * blockDim.x + threadIdx.x;   // 0..524287 per layer

        unsigned lane = t & 31;
        unsigned j    = (t >> 5) & 3;
        unsigned wn   = (t >> 7) & 1;
        unsigned ks   = (t >> 8) & 3;
        unsigned cc   = (t >> 10) & 31;
        unsigned nt   = (t >> 15);                // 0..15

        // global (n, k) this lane's fragment covers
        unsigned nbase = nt * 128 + wn * 64 + j * 16 + (lane >> 2);   // + {0,8}
        unsigned kbase = cc * 64 + ks * 16 + (lane & 3) * 2;          // + {0,1,8,9}
        unsigned nc = nbase >> 9, kc = kbase >> 9;

        const int   idxT[4][4] = {{0,1,2,3},{1,0,3,2},{2,3,0,1},{3,2,1,0}};
        const float sgnT[4][4] = {{ 1.f, 1.f, 1.f, 1.f},
                                  {-1.f, 1.f,-1.f, 1.f},
                                  {-1.f, 1.f, 1.f,-1.f},
                                  {-1.f,-1.f, 1.f, 1.f}};
        int   w = idxT[kc][nc];
        float s = sgnT[kc][nc];
        const float* W = layer2 ? (w == 0 ? w2r : w == 1 ? w2i : w == 2 ? w2j : w2k)
                                : (w == 0 ? w1r : w == 1 ? w1i : w == 2 ? w1j : w1k);
        const float* r0 = W + (size_t)(nbase & 511) * 512 + (kbase & 511);
        const float* r1 = r0 + 8 * 512;   // n+8 (stays within the 512-block)
        float2 p00 = *(const float2*)(r0);      // (k, k+1)   @ n
        float2 p01 = *(const float2*)(r0 + 8);  // (k+8, k+9) @ n
        float2 p10 = *(const float2*)(r1);      // (k, k+1)   @ n+8
        float2 p11 = *(const float2*)(r1 + 8);  // (k+8, k+9) @ n+8
        float v[8] = {s*p00.x, s*p00.y, s*p01.x, s*p01.y,
                      s*p10.x, s*p10.y, s*p11.x, s*p11.y};

        unsigned char* dst = (layer2 ? g_W2f : g_W1f)
            + (size_t)(((((nt * 32u + cc) * 4u + ks) * 2u + wn) * 4u + j) * 512u + lane * 16u);
        *(uint4*)dst = pack8(v);

        if (t < 2048) {
            int comp = t >> 9, d = t & 511;
            if (layer2) g_b2[t] = (comp == 0 ? b2r : comp == 1 ? b2i : comp == 2 ? b2j : b2k)[d];
            else        g_b1[t] = (comp == 0 ? b1r : comp == 1 ? b1i : comp == 2 ? b1j : b1k)[d];
        }
    }
}

// ============================================================================
// GEMM: C[128,128] per CTA, K = 2048, fp16 operands, fp32 accum.
// 4 warps (2m x 2n), warp tile 64x64, mma.sync.m16n8k16.
// A: 4-stage cp.async pipeline (depth-2 prefetch) + ldsm.
// B: coalesced LDG.128 of pre-shuffled fragments, register-double-buffered
//    (prefetch ks+1 while mma(ks)) — no smem, no ldsm, no STS for B.
// 2 CTAs/SM (launch_bounds(128,2)). Math order identical to champion.
// ============================================================================
__global__ void __launch_bounds__(128, 2) qgemm_kernel(int layer, float* __restrict__ out) {
    extern __shared__ __align__(1024) unsigned char smem[];
    uint32_t sb = smem_to_u32(smem);

    const __half* Ag  = (layer == 1) ? g_X : g_H;
    const unsigned char* Bf = (layer == 1) ? g_W1f : g_W2f;
    const float*  bias = (layer == 1) ? g_b1 : g_b2;

    int tid = threadIdx.x, lane = tid & 31, warp = tid >> 5;
    int wm = warp >> 1, wn = warp & 1;
    int ntN = blockIdx.x;
    int mtile = blockIdx.y * TM, ntile = ntN * TN;

    float acc[4][8][4];
#pragma unroll
    for (int i = 0; i < 4; i++)
#pragma unroll
        for (int j = 0; j < 8; j++)
#pragma unroll
            for (int k = 0; k < 4; k++) acc[i][j][k] = 0.f;

    auto issueA = [&](int c_) {
        if (c_ < NCH) {
            uint32_t st = sb + (c_ & 3) * A_STAGE_BYTES;
            int kk = c_ * 64;
            const __half* ap = Ag + (size_t)mtile * 2048 + kk;
#pragma unroll
            for (int i = 0; i < 8; i++) {     // A: 128 rows x 128B
                int idx = tid + i * 128;
                int r = idx >> 3, in16 = idx & 7;
                uint32_t d = st + swz((unsigned)(r * 128 + in16 * 16));
                cp_async16(d, (const char*)(ap + (size_t)r * 2048) + in16 * 16);
            }
        }
        asm volatile("cp.async.commit_group;" ::: "memory");
    };

    auto ldA = [&](uint32_t st, int ks, uint32_t a[4][4]) {
        int arow = wm * 64 + (lane & 15);
        int akb  = ks * 32 + ((lane >> 4) << 4);
#pragma unroll
        for (int im = 0; im < 4; im++)
            ldsm_x4(a[im], st + swz((unsigned)((arow + im * 16) * 128 + akb)));
    };

    // B fragment base for this warp's wn column (lane offset folded in)
    const unsigned char* bwbase = Bf + (size_t)((unsigned)ntN * 32u * 4u * 2u * 4u) * 512u
                                     + (unsigned)wn * (4u * 512u) + (unsigned)lane * 16u;
    auto ldgB = [&](int c_, int ks, uint32_t b[4][4]) {
        const unsigned char* p = bwbase + ((size_t)c_ * (4u * 2u * 4u) + (unsigned)ks * (2u * 4u)) * 512u;
#pragma unroll
        for (int j = 0; j < 4; j++) {
            uint4 v = *(const uint4*)(p + (unsigned)j * 512u);
            b[j][0] = v.x; b[j][1] = v.y; b[j][2] = v.z; b[j][3] = v.w;
        }
    };

    auto domma = [&](uint32_t a[4][4], uint32_t b[4][4]) {
#pragma unroll
        for (int im = 0; im < 4; im++)
#pragma unroll
            for (int j = 0; j < 4; j++) {
                mma16816(acc[im][2 * j],     a[im], b[j][0], b[j][1]);
                mma16816(acc[im][2 * j + 1], a[im], b[j][2], b[j][3]);
            }
    };

    issueA(0); issueA(1); issueA(2);

    uint32_t bA[4][4], bB[4][4];
    ldgB(0, 0, bA);

    for (int cc = 0; cc < NCH; cc++) {
        asm volatile("cp.async.wait_group 2;" ::: "memory");
        __syncthreads();
        uint32_t st = sb + (cc & 3) * A_STAGE_BYTES;
        issueA(cc + 3);

        uint32_t a[4][4];
        int cn = (cc + 1 < NCH) ? cc + 1 : 0;   // clamped (harmless dummy load on last chunk)
        // software pipeline: B fragments for the next ks prefetched during mma
        ldA(st, 0, a); ldgB(cc, 1, bB); domma(a, bA);
        ldA(st, 1, a); ldgB(cc, 2, bA); domma(a, bB);
        ldA(st, 2, a); ldgB(cc, 3, bB); domma(a, bA);
        ldA(st, 3, a); ldgB(cn, 0, bA); domma(a, bB);
    }

    __syncthreads();   // pipeline drained

    // ------------------------- epilogue (smem-staged) -------------------------
    if (layer == 1) {
        const unsigned RB = 272;     // padded fp16 row (256B data + 16B pad)
        unsigned char* shH = smem;   // 128*272 = 34816
#pragma unroll
        for (int im = 0; im < 4; im++) {
#pragma unroll
            for (int j = 0; j < 8; j++) {
                int nl = wn * 64 + j * 8 + (lane & 3) * 2;
                int ng = ntile + nl;
                float b0f = bias[ng], b1f = bias[ng + 1];
#pragma unroll
                for (int h = 0; h < 2; h++) {
                    int ml = wm * 64 + im * 16 + h * 8 + (lane >> 2);
                    float v0 = fmaxf(acc[im][j][h * 2 + 0] + b0f, 0.f);
                    float v1 = fmaxf(acc[im][j][h * 2 + 1] + b1f, 0.f);
                    *(__half2*)(shH + (unsigned)ml * RB + (unsigned)nl * 2) =
                        __halves2half2(__float2half_rn(v0), __float2half_rn(v1));
                }
            }
        }
        __syncthreads();
        int r = tid;   // one of 128 rows
        const uint4* sH = (const uint4*)(shH + (unsigned)r * RB);
        uint4* dH = (uint4*)(g_H + (size_t)(mtile + r) * 2048 + ntile);
#pragma unroll
        for (int k = 0; k < 16; k++) dH[k] = sH[k];
    } else {
        const unsigned RB = 528;     // padded fp32 row
        unsigned char* shF = smem;   // 128*528 = 67584
#pragma unroll
        for (int im = 0; im < 4; im++) {
#pragma unroll
            for (int j = 0; j < 8; j++) {
                int nl = wn * 64 + j * 8 + (lane & 3) * 2;
                int ng = ntile + nl;
                float b0f = bias[ng], b1f = bias[ng + 1];
#pragma unroll
                for (int h = 0; h < 2; h++) {
                    int ml = wm * 64 + im * 16 + h * 8 + (lane >> 2);
                    float2 v;
                    v.x = acc[im][j][h * 2 + 0] + b0f;
                    v.y = acc[im][j][h * 2 + 1] + b1f;
                    *(float2*)(shF + (unsigned)ml * RB + (unsigned)nl * 4) = v;
                }
            }
        }
        __syncthreads();
        int r = tid;
        int comp = ntile >> 9, dcol = ntile & 511;
        const uint4* sF = (const uint4*)(shF + (unsigned)r * RB);
        uint4* dF = (uint4*)(out + (size_t)comp * (32768ull * 512) + (size_t)(mtile + r) * 512 + dcol);
#pragma unroll
        for (int k = 0; k < 32; k++) dF[k] = sF[k];
    }
}

// ============================================================================
// Launch
// ============================================================================
extern "C" void kernel_launch(void* const* d_in, const int* in_sizes, int n_in,
                              void* d_out, int out_size) {
    const float* qr  = (const float*)d_in[0];
    const float* qi  = (const float*)d_in[1];
    const float* qj  = (const float*)d_in[2];
    const float* qk  = (const float*)d_in[3];
    const float* w1r = (const float*)d_in[4];
    const float* w1i = (const float*)d_in[5];
    const float* w1j = (const float*)d_in[6];
    const float* w1k = (const float*)d_in[7];
    const float* w2r = (const float*)d_in[8];
    const float* w2i = (const float*)d_in[9];
    const float* w2j = (const float*)d_in[10];
    const float* w2k = (const float*)d_in[11];
    const float* b1r = (const float*)d_in[12];
    const float* b1i = (const float*)d_in[13];
    const float* b1j = (const float*)d_in[14];
    const float* b1k = (const float*)d_in[15];
    const float* b2r = (const float*)d_in[16];
    const float* b2i = (const float*)d_in[17];
    const float* b2j = (const float*)d_in[18];
    const float* b2k = (const float*)d_in[19];
    float* out = (float*)d_out;

    cudaFuncSetAttribute(qgemm_kernel, cudaFuncAttributeMaxDynamicSharedMemorySize, SMEM_TOTAL);

    prep_all_kernel<<<36864, 256>>>(qr, qi, qj, qk,
                                    w1r, w1i, w1j, w1k, w2r, w2i, w2j, w2k,
                                    b1r, b1i, b1j, b1k, b2r, b2i, b2j, b2k);

    dim3 grid(16, 256);
    qgemm_kernel<<<grid, 128, SMEM_TOTAL>>>(1, out);
    qgemm_kernel<<<grid, 128, SMEM_TOTAL>>>(2, out);
}

// round 16
// speedup vs baseline: 1.1447x; 1.1447x over previous
#include <cuda_runtime.h>
#include <cuda_fp16.h>
#include <cstdint>

// ============================================================================
// Constants
// ============================================================================
#define NCH     32          // 32 chunks of K=64
#define TM      128
#define TN      128
#define STAGES  3
#define A_STAGE_BYTES (TM * 128)                      // 16384
#define B_STAGE_BYTES (TN * 128)                      // 16384
#define STAGE_BYTES   (A_STAGE_BYTES + B_STAGE_BYTES) // 32768
#define SMEM_TOTAL    (STAGES * STAGE_BYTES)          // 98304 -> 2 CTAs/SM

// ============================================================================
// Device-global scratch
// X / H: [32768, 2048] fp16 row-major
// W:     [2048, 2048] fp16 row-major (block weight matrix)
// ============================================================================
__device__ __align__(256) __half g_X[32768ull * 2048];
__device__ __align__(256) __half g_H[32768ull * 2048];
__device__ __align__(256) __half g_W1[2048ull * 2048];
__device__ __align__(256) __half g_W2[2048ull * 2048];
__device__ float g_b1[2048];
__device__ float g_b2[2048];

// ============================================================================
// Helpers
// ============================================================================
__device__ __forceinline__ uint32_t smem_to_u32(const void* p) {
    uint32_t a;
    asm("{ .reg .u64 t; cvta.to.shared.u64 t, %1; cvt.u32.u64 %0, t; }" : "=r"(a) : "l"(p));
    return a;
}

__device__ __forceinline__ unsigned swz(unsigned off) { return off ^ ((off >> 3) & 0x70); }

__device__ __forceinline__ void cp_async16(uint32_t dst, const void* src) {
    asm volatile("cp.async.cg.shared.global [%0], [%1], 16;" :: "r"(dst), "l"(src));
}

__device__ __forceinline__ void ldsm_x4(uint32_t r[4], uint32_t addr) {
    asm volatile("ldmatrix.sync.aligned.m8n8.x4.shared.b16 {%0,%1,%2,%3}, [%4];"
                 : "=r"(r[0]), "=r"(r[1]), "=r"(r[2]), "=r"(r[3]) : "r"(addr));
}

__device__ __forceinline__ void mma16816(float d[4], const uint32_t a[4], uint32_t b0, uint32_t b1) {
    asm volatile("mma.sync.aligned.m16n8k16.row.col.f32.f16.f16.f32 "
                 "{%0,%1,%2,%3}, {%4,%5,%6,%7}, {%8,%9}, {%0,%1,%2,%3};"
                 : "+f"(d[0]), "+f"(d[1]), "+f"(d[2]), "+f"(d[3])
                 : "r"(a[0]), "r"(a[1]), "r"(a[2]), "r"(a[3]), "r"(b0), "r"(b1));
}

// pack 8 fp32 -> 8 fp16 (uint4)
__device__ __forceinline__ uint4 pack8(const float* v) {
    unsigned h[4];
#pragma unroll
    for (int p = 0; p < 4; p++) {
        __half ha = __float2half_rn(v[2 * p]);
        __half hb = __float2half_rn(v[2 * p + 1]);
        h[p] = (unsigned)__half_as_ushort(ha) | ((unsigned)__half_as_ushort(hb) << 16);
    }
    return make_uint4(h[0], h[1], h[2], h[3]);
}

// ============================================================================
// Fused prep: conv_x (blocks [0,32768)) + weights/biases (blocks [32768,36864))
// ============================================================================
__global__ void prep_all_kernel(const float* __restrict__ qr, const float* __restrict__ qi,
                                const float* __restrict__ qj, const float* __restrict__ qk,
                                const float* __restrict__ w1r, const float* __restrict__ w1i,
                                const float* __restrict__ w1j, const float* __restrict__ w1k,
                                const float* __restrict__ w2r, const float* __restrict__ w2i,
                                const float* __restrict__ w2j, const float* __restrict__ w2k,
                                const float* b1r, const float* b1i, const float* b1j, const float* b1k,
                                const float* b2r, const float* b2i, const float* b2j, const float* b2k) {
    if (blockIdx.x < 32768) {
        // ---- conv_x: concatenate q components, cast to fp16 ----
        unsigned idx = blockIdx.x * blockDim.x + threadIdx.x;
        unsigned n  = idx >> 8;
        unsigned f0 = (idx & 255u) << 3;
        unsigned comp = f0 >> 9, d0 = f0 & 511;
        const float* src = (comp == 0 ? qr : comp == 1 ? qi : comp == 2 ? qj : qk);
        const float4* s4 = (const float4*)(src + (size_t)n * 512 + d0);
        float4 a = s4[0], b = s4[1];
        float v[8] = {a.x, a.y, a.z, a.w, b.x, b.y, b.z, b.w};
        *(uint4*)(g_X + (size_t)n * 2048 + f0) = pack8(v);
    } else {
        // ---- weight/bias prep ----
        unsigned pb = blockIdx.x - 32768;
        int layer2 = (pb >= 2048);
        unsigned idx = (pb & 2047u) * blockDim.x + threadIdx.x;
        unsigned o  = idx >> 8;
        unsigned i0 = (idx & 255u) << 3;
        unsigned oc = o >> 9, orow = o & 511;
        unsigned ic = i0 >> 9, ii = i0 & 511;

        const int   idxT[4][4] = {{0,1,2,3},{1,0,3,2},{2,3,0,1},{3,2,1,0}};
        const float sgnT[4][4] = {{ 1.f, 1.f, 1.f, 1.f},
                                  {-1.f, 1.f,-1.f, 1.f},
                                  {-1.f, 1.f, 1.f,-1.f},
                                  {-1.f,-1.f, 1.f, 1.f}};
        int   w = idxT[ic][oc];
        float s = sgnT[ic][oc];
        const float* W = layer2 ? (w == 0 ? w2r : w == 1 ? w2i : w == 2 ? w2j : w2k)
                                : (w == 0 ? w1r : w == 1 ? w1i : w == 2 ? w1j : w1k);
        const float4* s4 = (const float4*)(W + (size_t)orow * 512 + ii);
        float4 a = s4[0], b = s4[1];
        float v[8] = {s*a.x, s*a.y, s*a.z, s*a.w, s*b.x, s*b.y, s*b.z, s*b.w};

        __half* dst = (layer2 ? g_W2 : g_W1) + (size_t)o * 2048;
        *(uint4*)(dst + i0) = pack8(v);

        if (idx < 2048) {
            int comp = idx >> 9, d = idx & 511;
            if (layer2) g_b2[idx] = (comp == 0 ? b2r : comp == 1 ? b2i : comp == 2 ? b2j : b2k)[d];
            else        g_b1[idx] = (comp == 0 ? b1r : comp == 1 ? b1i : comp == 2 ? b1j : b1k)[d];
        }
    }
}

// ============================================================================
// GEMM: C[128,128] per CTA, K = 2048, fp16 operands, fp32 accum.
// 4 warps (2m x 2n), warp tile 64x64, mma.sync.m16n8k16.
// 3-stage cp.async pipeline (depth-2), 2 CTAs/SM (launch_bounds(128,2)).
// Cross-barrier fragment pipelining: frags for (cc+1, ks0) are loaded after
// an (almost free) wait_group+barrier placed BEFORE the last domma of chunk
// cc, so the post-barrier ldsm burst hides under MMAs and the first domma
// after every barrier consumes registers loaded in the previous chunk.
// Accumulation order identical to the round-12 champion.
// ============================================================================
__global__ void __launch_bounds__(128, 2) qgemm_kernel(int layer, float* __restrict__ out) {
    extern __shared__ __align__(1024) unsigned char smem[];
    uint32_t sb = smem_to_u32(smem);

    const __half* Ag   = (layer == 1) ? g_X  : g_H;
    const __half* Bg   = (layer == 1) ? g_W1 : g_W2;
    const float*  bias = (layer == 1) ? g_b1 : g_b2;

    int tid = threadIdx.x, lane = tid & 31, warp = tid >> 5;
    int wm = warp >> 1, wn = warp & 1;
    int mtile = blockIdx.y * TM, ntile = blockIdx.x * TN;

    float acc[4][8][4];
#pragma unroll
    for (int i = 0; i < 4; i++)
#pragma unroll
        for (int j = 0; j < 8; j++)
#pragma unroll
            for (int k = 0; k < 4; k++) acc[i][j][k] = 0.f;

    auto issue = [&](int c_) {
        if (c_ < NCH) {
            int s = c_ % STAGES;
            uint32_t st = sb + s * STAGE_BYTES;
            int kk = c_ * 64;
            const __half* ap = Ag + (size_t)mtile * 2048 + kk;
            const __half* bp = Bg + (size_t)ntile * 2048 + kk;
#pragma unroll
            for (int i = 0; i < 8; i++) {     // A: 128 rows x 128B
                int idx = tid + i * 128;
                int r = idx >> 3, in16 = idx & 7;
                uint32_t d = st + swz((unsigned)(r * 128 + in16 * 16));
                cp_async16(d, (const char*)(ap + (size_t)r * 2048) + in16 * 16);
            }
#pragma unroll
            for (int i = 0; i < 8; i++) {     // B: 128 rows x 128B
                int idx = tid + i * 128;
                int r = idx >> 3, in16 = idx & 7;
                uint32_t d = st + A_STAGE_BYTES + swz((unsigned)(r * 128 + in16 * 16));
                cp_async16(d, (const char*)(bp + (size_t)r * 2048) + in16 * 16);
            }
        }
        asm volatile("cp.async.commit_group;" ::: "memory");
    };

    auto ldA = [&](uint32_t st, int ks, uint32_t a[4][4]) {
        int arow = wm * 64 + (lane & 15);
        int akb  = ks * 32 + ((lane >> 4) << 4);
#pragma unroll
        for (int im = 0; im < 4; im++)
            ldsm_x4(a[im], st + swz((unsigned)((arow + im * 16) * 128 + akb)));
    };
    auto ldB = [&](uint32_t st, int ks, uint32_t b[4][4]) {
        int g    = lane >> 3;
        int brow = wn * 64 + (lane & 7) + ((g >> 1) << 3);
        int bkb  = ks * 32 + ((g & 1) << 4);
#pragma unroll
        for (int j = 0; j < 4; j++)
            ldsm_x4(b[j], st + A_STAGE_BYTES + swz((unsigned)((brow + j * 16) * 128 + bkb)));
    };
    auto domma = [&](uint32_t a[4][4], uint32_t b[4][4]) {
#pragma unroll
        for (int im = 0; im < 4; im++)
#pragma unroll
            for (int j = 0; j < 4; j++) {
                mma16816(acc[im][2 * j],     a[im], b[j][0], b[j][1]);
                mma16816(acc[im][2 * j + 1], a[im], b[j][2], b[j][3]);
            }
    };

    issue(0); issue(1);

    uint32_t a0[4][4], b0[4][4], a1[4][4], b1[4][4];

    // prologue: chunk 0 resident, preload its ks0 fragments
    asm volatile("cp.async.wait_group 1;" ::: "memory");
    __syncthreads();
    ldA(sb, 0, a0); ldB(sb, 0, b0);

    for (int cc = 0; cc < NCH; cc++) {
        uint32_t st = sb + (cc % STAGES) * STAGE_BYTES;

        ldA(st, 1, a1); ldB(st, 1, b1);     // ks1 frags (chunk cc resident)
        issue(cc + 2);                       // overlaps with compute below
        domma(a0, b0);                       // ks0 (preloaded last chunk)
        ldA(st, 2, a0); ldB(st, 2, b0);     // ks2
        domma(a1, b1);                       // ks1
        ldA(st, 3, a1); ldB(st, 3, b1);     // ks3
        domma(a0, b0);                       // ks2

        // publish chunk cc+1 CTA-wide: per-thread groups done + barrier
        asm volatile("cp.async.wait_group 1;" ::: "memory");
        __syncthreads();

        int cn = (cc + 1 < NCH) ? cc + 1 : cc;       // last iter: harmless re-read
        uint32_t stn = sb + (cn % STAGES) * STAGE_BYTES;
        ldA(stn, 0, a0); ldB(stn, 0, b0);   // next chunk ks0 — hides under domma
        domma(a1, b1);                       // ks3
    }

    __syncthreads();   // pipeline drained

    // ------------------------- epilogue (smem-staged) -------------------------
    if (layer == 1) {
        const unsigned RB = 272;     // padded fp16 row (256B data + 16B pad)
        unsigned char* shH = smem;   // 128*272 = 34816
#pragma unroll
        for (int im = 0; im < 4; im++) {
#pragma unroll
            for (int j = 0; j < 8; j++) {
                int nl = wn * 64 + j * 8 + (lane & 3) * 2;
                int ng = ntile + nl;
                float b0f = bias[ng], b1f = bias[ng + 1];
#pragma unroll
                for (int h = 0; h < 2; h++) {
                    int ml = wm * 64 + im * 16 + h * 8 + (lane >> 2);
                    float v0 = fmaxf(acc[im][j][h * 2 + 0] + b0f, 0.f);
                    float v1 = fmaxf(acc[im][j][h * 2 + 1] + b1f, 0.f);
                    *(__half2*)(shH + (unsigned)ml * RB + (unsigned)nl * 2) =
                        __halves2half2(__float2half_rn(v0), __float2half_rn(v1));
                }
            }
        }
        __syncthreads();
        int r = tid;   // one of 128 rows
        const uint4* sH = (const uint4*)(shH + (unsigned)r * RB);
        uint4* dH = (uint4*)(g_H + (size_t)(mtile + r) * 2048 + ntile);
#pragma unroll
        for (int k = 0; k < 16; k++) dH[k] = sH[k];
    } else {
        const unsigned RB = 528;     // padded fp32 row
        unsigned char* shF = smem;   // 128*528 = 67584
#pragma unroll
        for (int im = 0; im < 4; im++) {
#pragma unroll
            for (int j = 0; j < 8; j++) {
                int nl = wn * 64 + j * 8 + (lane & 3) * 2;
                int ng = ntile + nl;
                float b0f = bias[ng], b1f = bias[ng + 1];
#pragma unroll
                for (int h = 0; h < 2; h++) {
                    int ml = wm * 64 + im * 16 + h * 8 + (lane >> 2);
                    float2 v;
                    v.x = acc[im][j][h * 2 + 0] + b0f;
                    v.y = acc[im][j][h * 2 + 1] + b1f;
                    *(float2*)(shF + (unsigned)ml * RB + (unsigned)nl * 4) = v;
                }
            }
        }
        __syncthreads();
        int r = tid;
        int comp = ntile >> 9, dcol = ntile & 511;
        const uint4* sF = (const uint4*)(shF + (unsigned)r * RB);
        uint4* dF = (uint4*)(out + (size_t)comp * (32768ull * 512) + (size_t)(mtile + r) * 512 + dcol);
#pragma unroll
        for (int k = 0; k < 32; k++) dF[k] = sF[k];
    }
}

// ============================================================================
// Launch
// ============================================================================
extern "C" void kernel_launch(void* const* d_in, const int* in_sizes, int n_in,
                              void* d_out, int out_size) {
    const float* qr  = (const float*)d_in[0];
    const float* qi  = (const float*)d_in[1];
    const float* qj  = (const float*)d_in[2];
    const float* qk  = (const float*)d_in[3];
    const float* w1r = (const float*)d_in[4];
    const float* w1i = (const float*)d_in[5];
    const float* w1j = (const float*)d_in[6];
    const float* w1k = (const float*)d_in[7];
    const float* w2r = (const float*)d_in[8];
    const float* w2i = (const float*)d_in[9];
    const float* w2j = (const float*)d_in[10];
    const float* w2k = (const float*)d_in[11];
    const float* b1r = (const float*)d_in[12];
    const float* b1i = (const float*)d_in[13];
    const float* b1j = (const float*)d_in[14];
    const float* b1k = (const float*)d_in[15];
    const float* b2r = (const float*)d_in[16];
    const float* b2i = (const float*)d_in[17];
    const float* b2j = (const float*)d_in[18];
    const float* b2k = (const float*)d_in[19];
    float* out = (float*)d_out;

    cudaFuncSetAttribute(qgemm_kernel, cudaFuncAttributeMaxDynamicSharedMemorySize, SMEM_TOTAL);

    prep_all_kernel<<<36864, 256>>>(qr, qi, qj, qk,
                                    w1r, w1i, w1j, w1k, w2r, w2i, w2j, w2k,
                                    b1r, b1i, b1j, b1k, b2r, b2i, b2j, b2k);

    dim3 grid(16, 256);
    qgemm_kernel<<<grid, 128, SMEM_TOTAL>>>(1, out);
    qgemm_kernel<<<grid, 128, SMEM_TOTAL>>>(2, out);
}